// round 17
// baseline (speedup 1.0000x reference)
#include <cuda_runtime.h>
#include <cuda_fp16.h>
#include <cstdint>

// ---------------------------------------------------------------------------
// Problem dims
// ---------------------------------------------------------------------------
static constexpr int BATCH = 16;
static constexpr int LQ    = 2048;
static constexpr int LK    = 2048;
static constexpr int DIM   = 128;
static constexpr float SCALE_LOG2E = 0.08838834764831845f * 1.4426950408889634f;

static constexpr size_t NEL  = (size_t)BATCH * LQ * DIM;
static constexpr size_t NELE = (size_t)BATCH * LQ * LK;

// fp16 scratch (device globals = allowed scratch)
__device__ __half g_Khi[NEL];
__device__ __half g_Vhi[NEL];
__device__ __half g_E[NELE];          // unnormalized exp(S), fp16

// ---------------------------------------------------------------------------
// PTX helpers (sm_80-class only)
// ---------------------------------------------------------------------------
__device__ __forceinline__ uint32_t smem_u32(const void* p) {
    uint32_t a;
    asm("{ .reg .u64 t; cvta.to.shared.u64 t, %1; cvt.u32.u64 %0, t; }" : "=r"(a) : "l"(p));
    return a;
}
__device__ __forceinline__ float ex2(float x) {
    float r; asm("ex2.approx.f32 %0, %1;" : "=f"(r) : "f"(x)); return r;
}
__device__ __forceinline__ void ldsm4(uint32_t (&r)[4], uint32_t addr) {
    asm volatile("ldmatrix.sync.aligned.m8n8.x4.shared.b16 {%0,%1,%2,%3}, [%4];"
                 : "=r"(r[0]), "=r"(r[1]), "=r"(r[2]), "=r"(r[3]) : "r"(addr));
}
__device__ __forceinline__ void ldsm4t(uint32_t (&r)[4], uint32_t addr) {
    asm volatile("ldmatrix.sync.aligned.m8n8.x4.trans.shared.b16 {%0,%1,%2,%3}, [%4];"
                 : "=r"(r[0]), "=r"(r[1]), "=r"(r[2]), "=r"(r[3]) : "r"(addr));
}
__device__ __forceinline__ void mma16816(float (&d)[4], const uint32_t (&a)[4],
                                         uint32_t b0, uint32_t b1) {
    asm volatile(
        "mma.sync.aligned.m16n8k16.row.col.f32.f16.f16.f32 "
        "{%0,%1,%2,%3},{%4,%5,%6,%7},{%8,%9},{%0,%1,%2,%3};"
        : "+f"(d[0]), "+f"(d[1]), "+f"(d[2]), "+f"(d[3])
        : "r"(a[0]), "r"(a[1]), "r"(a[2]), "r"(a[3]), "r"(b0), "r"(b1));
}
__device__ __forceinline__ void cp16(uint32_t smem, const void* g) {
    asm volatile("cp.async.cg.shared.global [%0], [%1], 16;" :: "r"(smem), "l"(g) : "memory");
}
__device__ __forceinline__ void cp_commit() { asm volatile("cp.async.commit_group;" ::: "memory"); }
__device__ __forceinline__ void cp_wait0()  { asm volatile("cp.async.wait_group 0;" ::: "memory"); }
__device__ __forceinline__ void barg(int id) {   // named barrier, 128 threads
    asm volatile("bar.sync %0, 128;" :: "r"(id) : "memory");
}

__device__ __forceinline__ uint32_t packh2(__half a, __half b) {
    __half2 p{a, b};
    return *reinterpret_cast<uint32_t*>(&p);
}

// ---------------------------------------------------------------------------
// Kernel 0: preconvert K / V -> fp16 (Q handled inside fused kernel)
// ---------------------------------------------------------------------------
__global__ __launch_bounds__(256) void preconvert_kernel(const float* __restrict__ K,
                                                         const float* __restrict__ V) {
    const size_t t = (size_t)blockIdx.x * 256 + threadIdx.x;
    const int which = blockIdx.y;
    const float* src = (which == 0) ? K : V;
    __half* dst = (which == 0) ? g_Khi : g_Vhi;

    float4 v = reinterpret_cast<const float4*>(src)[t];
    uint2 hh{packh2(__float2half_rn(v.x), __float2half_rn(v.y)),
             packh2(__float2half_rn(v.z), __float2half_rn(v.w))};
    reinterpret_cast<uint2*>(dst)[t] = hh;
}

// ---------------------------------------------------------------------------
// Fused attention kernel (pure fp16 QK/PV, fp32 accum + fp32 exp).
// Each CTA: two 64-row q-tiles; tile0's P-tail interleaved into tile1's loop.
// 8 warps = two independent 128-thread groups (named barriers); group wn owns
// 32-k blocks with (block & 1) == wn.
// SOFTWARE PIPELINE: iter kc runs QK(kc) and PV(kc-1) concurrently
// (sh kept in registers, V triple-buffered, K double-buffered).
// ---------------------------------------------------------------------------
static constexpr int RSB    = 272;                  // padded row stride (bytes)
static constexpr int OFF_Q  = 0;
static constexpr int QT     = 64 * RSB;             // 17408
static constexpr int OFF_ST = QT;                   // 17408
static constexpr int KSZ    = 32 * RSB;             // 8704 (32 k-rows)
static constexpr int GBUF   = 5 * KSZ;              // 2 K stages + 3 V stages
static constexpr int OFF_INV = OFF_ST + 2 * GBUF;   // 104448
static constexpr int SMEM_BYTES = OFF_INV + 1024;   // 105472

__global__ __launch_bounds__(256, 2) void fused_attn_kernel(const float* __restrict__ Qf,
                                                            float* __restrict__ P,
                                                            float* __restrict__ R) {
    extern __shared__ char sm[];
    const uint32_t sb = smem_u32(sm);

    const int tid = threadIdx.x, lane = tid & 31, wid = tid >> 5;
    const int wm = wid & 3, wn = wid >> 2;
    const int gtid = tid & 127;
    const int g = lane >> 2, c2 = (lane & 3) * 2;
    const int b = blockIdx.y;
    const int qt0 = blockIdx.x * 128;

    const size_t kvbase = (size_t)b * LK * DIM;
    const uint32_t gbase = sb + OFF_ST + (uint32_t)(wn * GBUF);
    // group buffer layout: K stages at 0,KSZ ; V stages at 2K,3K,4K
    const uint32_t vstg = gbase + 2 * KSZ;

    const uint32_t aoff  = (uint32_t)((lane & 15) * RSB + (lane >> 4) * 16);
    const uint32_t boff  = (uint32_t)(((lane & 7) + (lane >> 4) * 8) * RSB + ((lane >> 3) & 1) * 16);
    const uint32_t boffT = (uint32_t)(((lane & 7) + ((lane >> 3) & 1) * 8) * RSB + (lane >> 4) * 16);
    const uint32_t qaHi  = sb + OFF_Q + (uint32_t)(wm * 16) * RSB + aoff;

    float* partial = reinterpret_cast<float*>(sm + OFF_INV);
    float* inv     = reinterpret_cast<float*>(sm + OFF_INV + 256);

#pragma unroll
    for (int tile = 0; tile < 2; ++tile) {
        const int qt = qt0 + tile * 64;

        // ---- stage Q: load fp32, scale, convert, STS (all 256 threads) ----
        {
            const float* Qb = Qf + ((size_t)b * LQ + qt) * DIM;
#pragma unroll
            for (int it = 0; it < 8; ++it) {
                int i = tid + it * 256;                 // 0..2047 float4
                int row = i >> 5, col4 = (i & 31) * 4;
                float4 v = *reinterpret_cast<const float4*>(Qb + (size_t)row * DIM + col4);
                v.x *= SCALE_LOG2E; v.y *= SCALE_LOG2E; v.z *= SCALE_LOG2E; v.w *= SCALE_LOG2E;
                uint2 hh{packh2(__float2half_rn(v.x), __float2half_rn(v.y)),
                         packh2(__float2half_rn(v.z), __float2half_rn(v.w))};
                *reinterpret_cast<uint2*>(sm + OFF_Q + row * RSB + col4 * 2) = hh;
            }
        }
        // ---- stage chunk 0 for this group (K slot 0, V slot 0) ----
        {
            const size_t kb = kvbase + (size_t)(wn * 32) * DIM;
#pragma unroll
            for (int it = 0; it < 4; ++it) {
                int i = gtid + it * 128;
                int row = i >> 4, chk = i & 15;
                uint32_t so = (uint32_t)(row * RSB + chk * 16);
                const size_t gg = kb + (size_t)row * DIM + chk * 8;
                cp16(gbase + so,      g_Khi + gg);
                cp16(vstg + so,       g_Vhi + gg);
            }
            cp_commit(); cp_wait0();
        }
        __syncthreads();   // Q visible + chunk 0 staged (+ prev-tile smem safe)

        float racc[16][4];
#pragma unroll
        for (int j = 0; j < 16; ++j)
#pragma unroll
            for (int c = 0; c < 4; ++c) racc[j][c] = 0.f;
        float rs0 = 0.f, rs1 = 0.f;

        __half* E0 = g_E + ((size_t)b * LQ + qt + wm * 16 + g) * LK + wn * 32 + c2;
        __half* E1 = E0 + (size_t)8 * LK;

        // tile0 tail sources (used when tile==1)
        const __half* Es0 = g_E + ((size_t)b * LQ + qt0) * LK;
        float* Pt0 = P + ((size_t)b * LQ + qt0) * LK;

        // pipeline state: sh of previous chunk, V rotating slots
        uint32_t pA[4], pB[4];                       // sh_prev halves
        int vprev_s = 2, vcur_s = 0, vnext_s = 1;    // V slot indices (mod 3)
        (void)vcur_s;

#pragma unroll 1
        for (int kc = 0; kc < 32; ++kc) {
            // prefetch chunk kc+1 (K slot (kc+1)&1, V slot vnext_s)
            if (kc < 31) {
                const uint32_t kdst = gbase + (uint32_t)(((kc + 1) & 1) * KSZ);
                const uint32_t vdst = vstg + (uint32_t)(vnext_s * KSZ);
                const size_t kb = kvbase + (size_t)((kc + 1) * 64 + wn * 32) * DIM;
#pragma unroll
                for (int it = 0; it < 4; ++it) {
                    int i = gtid + it * 128;
                    int row = i >> 4, chk = i & 15;
                    uint32_t so = (uint32_t)(row * RSB + chk * 16);
                    const size_t gg = kb + (size_t)row * DIM + chk * 8;
                    cp16(kdst + so, g_Khi + gg);
                    cp16(vdst + so, g_Vhi + gg);
                }
                cp_commit();
            }

            // ---- QK(kc): two 16-k halves from K slot kc&1 ----
            float s0[2][4], s1[2][4];
#pragma unroll
            for (int j = 0; j < 2; ++j)
#pragma unroll
                for (int c = 0; c < 4; ++c) { s0[j][c] = 0.f; s1[j][c] = 0.f; }

            const uint32_t kh = gbase + (uint32_t)((kc & 1) * KSZ) + boff;
#pragma unroll
            for (int ks = 0; ks < 8; ++ks) {
                uint32_t qh[4], bh0[4], bh1[4];
                ldsm4(qh,  qaHi + ks * 32);
                ldsm4(bh0, kh + ks * 32);
                ldsm4(bh1, kh + 16 * RSB + ks * 32);
                mma16816(s0[0], qh, bh0[0], bh0[1]);
                mma16816(s0[1], qh, bh0[2], bh0[3]);
                mma16816(s1[0], qh, bh1[0], bh1[1]);
                mma16816(s1[1], qh, bh1[2], bh1[3]);
            }

            // ---- PV(kc-1): independent of QK(kc); V slot vprev_s ----
            if (kc > 0) {
                const uint32_t vb = vstg + (uint32_t)(vprev_s * KSZ) + boffT;
#pragma unroll
                for (int nb = 0; nb < 8; ++nb) {
                    uint32_t bv[4];
                    ldsm4t(bv, vb + nb * 32);
                    mma16816(racc[nb * 2],     pA, bv[0], bv[1]);
                    mma16816(racc[nb * 2 + 1], pA, bv[2], bv[3]);
                }
#pragma unroll
                for (int nb = 0; nb < 8; ++nb) {
                    uint32_t bv[4];
                    ldsm4t(bv, vb + 16 * RSB + nb * 32);
                    mma16816(racc[nb * 2],     pB, bv[0], bv[1]);
                    mma16816(racc[nb * 2 + 1], pB, bv[2], bv[3]);
                }
            }

            // ---- exp2(kc), rowsums, pack fp16 A-frags ----
            float e0[2][4], e1[2][4];
#pragma unroll
            for (int j = 0; j < 2; ++j) {
                e0[j][0] = ex2(s0[j][0]); e0[j][1] = ex2(s0[j][1]);
                e0[j][2] = ex2(s0[j][2]); e0[j][3] = ex2(s0[j][3]);
                e1[j][0] = ex2(s1[j][0]); e1[j][1] = ex2(s1[j][1]);
                e1[j][2] = ex2(s1[j][2]); e1[j][3] = ex2(s1[j][3]);
                rs0 += e0[j][0] + e0[j][1] + e1[j][0] + e1[j][1];
                rs1 += e0[j][2] + e0[j][3] + e1[j][2] + e1[j][3];
            }
            uint32_t sh0[4], sh1[4];
#pragma unroll
            for (int j = 0; j < 2; ++j) {
                sh0[j * 2 + 0] = packh2(__float2half_rn(e0[j][0]), __float2half_rn(e0[j][1]));
                sh0[j * 2 + 1] = packh2(__float2half_rn(e0[j][2]), __float2half_rn(e0[j][3]));
                sh1[j * 2 + 0] = packh2(__float2half_rn(e1[j][0]), __float2half_rn(e1[j][1]));
                sh1[j * 2 + 1] = packh2(__float2half_rn(e1[j][2]), __float2half_rn(e1[j][3]));
            }

            // ---- store E fp16 (drains in background) ----
            *reinterpret_cast<uint32_t*>(E0 + kc * 64)      = sh0[0];
            *reinterpret_cast<uint32_t*>(E1 + kc * 64)      = sh0[1];
            *reinterpret_cast<uint32_t*>(E0 + kc * 64 + 8)  = sh0[2];
            *reinterpret_cast<uint32_t*>(E1 + kc * 64 + 8)  = sh0[3];
            *reinterpret_cast<uint32_t*>(E0 + kc * 64 + 16) = sh1[0];
            *reinterpret_cast<uint32_t*>(E1 + kc * 64 + 16) = sh1[1];
            *reinterpret_cast<uint32_t*>(E0 + kc * 64 + 24) = sh1[2];
            *reinterpret_cast<uint32_t*>(E1 + kc * 64 + 24) = sh1[3];

            // rotate sh into prev
#pragma unroll
            for (int c = 0; c < 4; ++c) { pA[c] = sh0[c]; pB[c] = sh1[c]; }

            // ---- interleaved tile0 tail (tile 1 only) ----
            if (tile == 1) {
#pragma unroll
                for (int u = 0; u < 2; ++u) {
                    int idx = tid + (kc * 2 + u) * 256;   // 0..16383
                    int r = idx >> 8, c8 = idx & 255;
                    const uint4 hv = *reinterpret_cast<const uint4*>(Es0 + (size_t)r * LK + c8 * 8);
                    const float iv = inv[r];
                    const __half2* hp = reinterpret_cast<const __half2*>(&hv);
                    float2 f0 = __half22float2(hp[0]), f1 = __half22float2(hp[1]);
                    float2 f2 = __half22float2(hp[2]), f3 = __half22float2(hp[3]);
                    float4 o0{f0.x * iv, f0.y * iv, f1.x * iv, f1.y * iv};
                    float4 o1{f2.x * iv, f2.y * iv, f3.x * iv, f3.y * iv};
                    float* pd = Pt0 + (size_t)r * LK + c8 * 8;
                    *reinterpret_cast<float4*>(pd)     = o0;
                    *reinterpret_cast<float4*>(pd + 4) = o1;
                }
            }

            // rotate V slots
            int t = vprev_s; vprev_s = vcur_s; vcur_s = vnext_s; vnext_s = t;

            cp_wait0();
            barg(wn + 1);
        }

        // ---- trailing PV(31): V slot vprev_s (before smem reduce reuse) ----
        {
            const uint32_t vb = vstg + (uint32_t)(vprev_s * KSZ) + boffT;
#pragma unroll
            for (int nb = 0; nb < 8; ++nb) {
                uint32_t bv[4];
                ldsm4t(bv, vb + nb * 32);
                mma16816(racc[nb * 2],     pA, bv[0], bv[1]);
                mma16816(racc[nb * 2 + 1], pA, bv[2], bv[3]);
            }
#pragma unroll
            for (int nb = 0; nb < 8; ++nb) {
                uint32_t bv[4];
                ldsm4t(bv, vb + 16 * RSB + nb * 32);
                mma16816(racc[nb * 2],     pB, bv[0], bv[1]);
                mma16816(racc[nb * 2 + 1], pB, bv[2], bv[3]);
            }
        }

        // ---- cross-warp combine (wn pairs), rowsums, R store ----
        rs0 += __shfl_xor_sync(0xFFFFFFFFu, rs0, 1);
        rs0 += __shfl_xor_sync(0xFFFFFFFFu, rs0, 2);
        rs1 += __shfl_xor_sync(0xFFFFFFFFu, rs1, 1);
        rs1 += __shfl_xor_sync(0xFFFFFFFFu, rs1, 2);

        __syncthreads();   // all mainloop smem reads done

        if (wn == 1) {
            float4* red = reinterpret_cast<float4*>(sm + wm * 8192);
#pragma unroll
            for (int j = 0; j < 16; ++j)
                red[j * 32 + lane] = *reinterpret_cast<float4*>(racc[j]);
            if ((lane & 3) == 0) {
                partial[wm * 16 + g]     = rs0;
                partial[wm * 16 + 8 + g] = rs1;
            }
        }
        __syncthreads();

        if (wn == 0) {
            const float4* red = reinterpret_cast<const float4*>(sm + wm * 8192);
#pragma unroll
            for (int j = 0; j < 16; ++j) {
                float4 o = red[j * 32 + lane];
                racc[j][0] += o.x; racc[j][1] += o.y; racc[j][2] += o.z; racc[j][3] += o.w;
            }
            const int row0 = wm * 16 + g, row1 = row0 + 8;
            const float iv0 = 1.f / (rs0 + partial[row0]);
            const float iv1 = 1.f / (rs1 + partial[row1]);
            if ((lane & 3) == 0) { inv[row0] = iv0; inv[row1] = iv1; }

            float* Rp = R + ((size_t)b * LQ + qt + row0) * DIM + c2;
#pragma unroll
            for (int j = 0; j < 16; ++j) {
                float2 v0{racc[j][0] * iv0, racc[j][1] * iv0};
                float2 v1{racc[j][2] * iv1, racc[j][3] * iv1};
                *reinterpret_cast<float2*>(Rp + j * 8)           = v0;
                *reinterpret_cast<float2*>(Rp + 8 * DIM + j * 8) = v1;
            }
        }
        __syncthreads();   // inv[] valid for this tile's tail
    }

    // ---- exposed tail: normalize tile 1's P (tile 0 was interleaved) ----
    const __half* Es = g_E + ((size_t)b * LQ + qt0 + 64) * LK;
    float* Pt = P + ((size_t)b * LQ + qt0 + 64) * LK;
#pragma unroll 4
    for (int it = 0; it < 64; ++it) {
        int idx = tid + it * 256;          // 0..16383 uint4 slots (8 halves each)
        int r = idx >> 8, c8 = idx & 255;
        const uint4 hv = *reinterpret_cast<const uint4*>(Es + (size_t)r * LK + c8 * 8);
        const float iv = inv[r];
        const __half2* hp = reinterpret_cast<const __half2*>(&hv);
        float2 f0 = __half22float2(hp[0]), f1 = __half22float2(hp[1]);
        float2 f2 = __half22float2(hp[2]), f3 = __half22float2(hp[3]);
        float4 o0{f0.x * iv, f0.y * iv, f1.x * iv, f1.y * iv};
        float4 o1{f2.x * iv, f2.y * iv, f3.x * iv, f3.y * iv};
        float* pd = Pt + (size_t)r * LK + c8 * 8;
        *reinterpret_cast<float4*>(pd)     = o0;
        *reinterpret_cast<float4*>(pd + 4) = o1;
    }
}

// ---------------------------------------------------------------------------
// Launch: d_out = [ R | P ]
// ---------------------------------------------------------------------------
extern "C" void kernel_launch(void* const* d_in, const int* in_sizes, int n_in,
                              void* d_out, int out_size) {
    const float* Q = (const float*)d_in[0];
    const float* K = (const float*)d_in[1];
    const float* V = (const float*)d_in[2];
    float* R = (float*)d_out;
    float* P = (float*)d_out + (size_t)BATCH * LQ * DIM;

    cudaFuncSetAttribute(fused_attn_kernel, cudaFuncAttributeMaxDynamicSharedMemorySize, SMEM_BYTES);

    {
        dim3 grid((unsigned)(NEL / 4 / 256), 2);
        preconvert_kernel<<<grid, 256>>>(K, V);
    }
    {
        dim3 grid(LQ / 128, BATCH);
        fused_attn_kernel<<<grid, 256, SMEM_BYTES>>>(Q, P, R);
    }
}